// round 10
// baseline (speedup 1.0000x reference)
#include <cuda_runtime.h>
#include <cuda_fp16.h>
#include <math.h>
#include <stdint.h>

// Problem constants
#define B_    32
#define N_    256
#define E_    1024
#define T_    5
#define ANNO_ 18
#define AACT_ 3
#define BN_   8192
#define DEC_IN_ 1216   // E + ND + 2*VD

// ---------------- scratch (static device globals; no allocation) -------------
__device__ float g_h  [BN_ * E_];          // encoder hidden  [8192,1024]
__device__ float g_gi [BN_ * 3 * E_];      // encoder gi      [8192,3072]
__device__ float g_gh [BN_ * 3 * E_];      // encoder gh      [8192,3072]
__device__ float g_gid[BN_ * 6 * E_];      // decoder gi      [8192,6144]
__device__ float g_mid[BN_ * E_];          // relu layer      [8192,1024]
__device__ float g_out3[BN_ * AACT_];
__device__ float g_vn[B_ * 64];
__device__ float g_va[B_ * 64];
__device__ float g_maxv[B_];

// fp16 3-term split operands (merged-K layouts)
// weights:      [hi|hi|lo]   activations: [hi|lo|hi]
// => sum = A_hi*W_hi + A_lo*W_hi + A_hi*W_lo  (residual ~2^-22)
__device__ __align__(256) __half g_Wihp [3072 * 6144];    // K=2048 -> 6144
__device__ __align__(256) __half g_Whhp [3072 * 3072];    // K=1024 -> 3072
__device__ __align__(256) __half g_dWihp[6144 * 3648];    // K=1216 -> 3648
__device__ __align__(256) __half g_W1p  [1024 * 6144];    // K=2048 -> 6144
__device__ __align__(256) __half g_adjO [B_ * 256 * 512]; // [A|A] exact
__device__ __align__(256) __half g_adjI [B_ * 256 * 512];
__device__ __align__(256) __half g_ap   [BN_ * 6144];     // a'  [hi|lo|hi]
__device__ __align__(256) __half g_hp   [BN_ * 3072];     // h'  [hi|lo|hi]
__device__ __align__(256) __half g_ht   [B_ * 1024 * 512];// h^T [hi|lo] K=256x2
__device__ __align__(256) __half g_cp   [BN_ * 3648];     // concat' [hi|lo|hi]
__device__ __align__(256) __half g_hidp [BN_ * 6144];     // hidden' [hi|lo|hi]

// ---------------- helpers -----------------------------------------------------
__device__ __forceinline__ uint32_t s2u(const void* p) {
    uint32_t a;
    asm("{ .reg .u64 t; cvta.to.shared.u64 t, %1; cvt.u32.u64 %0, t; }" : "=r"(a) : "l"(p));
    return a;
}
__device__ __forceinline__ uint64_t g2u(const void* p) {
    uint64_t a;
    asm("cvta.to.global.u64 %0, %1;" : "=l"(a) : "l"(p));
    return a;
}

#define CP_ASYNC16(smem_u32, gptr64) \
    asm volatile("cp.async.cg.shared.global [%0], [%1], 16;" :: "r"(smem_u32), "l"(gptr64))
#define CP_COMMIT() asm volatile("cp.async.commit_group;" ::: "memory")
#define CP_WAIT(n)  asm volatile("cp.async.wait_group %0;" :: "n"(n) : "memory")

#define LDSM4(r0, r1, r2, r3, addr)                                           \
    asm volatile("ldmatrix.sync.aligned.m8n8.x4.shared.b16 {%0,%1,%2,%3}, [%4];" \
                 : "=r"(r0), "=r"(r1), "=r"(r2), "=r"(r3) : "r"(addr))

#define MMA16816(d, a, b)                                                     \
    asm volatile(                                                             \
        "mma.sync.aligned.m16n8k16.row.col.f32.f16.f16.f32 "                  \
        "{%0,%1,%2,%3}, {%4,%5,%6,%7}, {%8,%9}, {%0,%1,%2,%3};"               \
        : "+f"((d)[0]), "+f"((d)[1]), "+f"((d)[2]), "+f"((d)[3])              \
        : "r"((a)[0]), "r"((a)[1]), "r"((a)[2]), "r"((a)[3]),                 \
          "r"((b)[0]), "r"((b)[1]))

// ---------------- mma.sync GEMM: C[M,N] = A[M,K'] * B[N,K']^T -----------------
// A,B fp16 row-major K-major. CTA tile 128x128, BK=64 (128B rows).
// 4 warps, each owning a 64x64 warp tile (acc = 128 f32/thread).
// XOR-swizzled SMEM (chunk ^ row&7) + ldmatrix.x4. 3-stage cp.async pipeline,
// 96KB dynamic smem, 2 CTA/SM.
// Epilogue: spl==null -> f32 (+bias)(+relu) into C;
//           spl!=null -> 3-term fp16 split [hi|lo|hi], pitch splPitch, section
//                        width splK, column offset splColOff.
#define STAGE_BYTES 32768      // A 16KB + B 16KB
#define B_OFF       16384
#define SMEM_TOTAL_GEMM (3 * STAGE_BYTES)

__global__ __launch_bounds__(128, 2)
void gemm_mma(const __half* __restrict__ A, const __half* __restrict__ Bm,
              int Kp, long long sA, long long sB,
              float* __restrict__ C, int ldc, long long sC,
              const float* __restrict__ bias, int relu,
              __half* __restrict__ spl, int splPitch, int splK, int splColOff,
              long long sSpl)
{
    extern __shared__ char smem[];
    const uint32_t smb = s2u(smem);

    const int tid  = threadIdx.x;
    const int wid  = tid >> 5, lane = tid & 31;
    const int g    = lane >> 2, tig = lane & 3;
    const int wm0  = (wid & 1) * 64;
    const int wn0  = (wid >> 1) * 64;
    const int z    = blockIdx.z;

    const __half* Ab = A  + (long long)z * sA + (long long)(blockIdx.y * 128) * Kp;
    const __half* Bb = Bm + (long long)z * sB + (long long)(blockIdx.x * 128) * Kp;

    // ---- cp.async coords: 1024 16B chunks per operand per stage, 8/thread ----
    // row r = rbase + 16*i  (i=0..7); (r & 7) == (rbase & 7) so the swizzle
    // offset is invariant across i -> constant-offset addressing.
    const int rbase = tid >> 3;            // 0..15
    const int ch    = tid & 7;             // 16B chunk within 128B row
    const long long pitchB = (long long)Kp * 2;
    const uint64_t gA0 = g2u((const char*)Ab + (long long)rbase * pitchB + ch * 16);
    const uint64_t gB0 = g2u((const char*)Bb + (long long)rbase * pitchB + ch * 16);
    const long long rstep = 16 * pitchB;
    const uint32_t sw  = (uint32_t)((ch ^ (rbase & 7)) << 4);
    const uint32_t sA0 = smb + rbase * 128 + sw;
    const uint32_t sB0 = smb + B_OFF + rbase * 128 + sw;

#define LOAD_STAGE(s, idx)                                                 \
    do {                                                                   \
        const long long kB = (long long)(idx) * 128;                       \
        const uint32_t so = (uint32_t)(s) * STAGE_BYTES;                   \
        _Pragma("unroll")                                                  \
        for (int i_ = 0; i_ < 8; i_++) {                                   \
            CP_ASYNC16(sA0 + so + i_ * 2048, gA0 + kB + i_ * rstep);       \
            CP_ASYNC16(sB0 + so + i_ * 2048, gB0 + kB + i_ * rstep);       \
        }                                                                  \
    } while (0)

    // ---- ldmatrix per-lane constants ----
    const int xorL = lane & 7;
    const int cA   = lane >> 4;            // 0/1: k-halves of 16x16 A matrices
    const int cB   = (lane >> 3) & 1;      // 0/1: k-halves of B matrices
    uint32_t aoff[4], boff[4];
#pragma unroll
    for (int i = 0; i < 4; i++)
        aoff[i] = (uint32_t)(wm0 + i * 16 + (lane & 15)) * 128;
#pragma unroll
    for (int jp = 0; jp < 4; jp++)
        boff[jp] = (uint32_t)(wn0 + jp * 16 + (lane & 7) + ((lane & 16) >> 1)) * 128 + B_OFF;

    float acc[4][8][4];
#pragma unroll
    for (int i = 0; i < 4; i++)
#pragma unroll
        for (int j = 0; j < 8; j++)
#pragma unroll
            for (int c = 0; c < 4; c++) acc[i][j][c] = 0.f;

    const int nIter = Kp >> 6;

    // prologue: stages 0,1
    LOAD_STAGE(0, 0); CP_COMMIT();
    if (nIter > 1) LOAD_STAGE(1, 1);
    CP_COMMIT();

    int stage = 0;
    for (int it = 0; it < nIter; ++it) {
        CP_WAIT(1);           // stage `it` complete (empty-commit discipline)
        __syncthreads();      // all warps done reading stage it-1

        if (it + 2 < nIter) {
            int ns = stage + 2; if (ns >= 3) ns -= 3;
            LOAD_STAGE(ns, it + 2);
        }
        CP_COMMIT();          // always commit (possibly empty group)

        const uint32_t sAs = smb + stage * STAGE_BYTES;
#pragma unroll
        for (int ks = 0; ks < 4; ks++) {
            const int c2 = ks * 2;
            uint32_t af[4][4], bf[8][2];
#pragma unroll
            for (int i = 0; i < 4; i++) {
                const uint32_t ad = sAs + aoff[i] + (uint32_t)((((c2 + cA) ^ xorL)) << 4);
                LDSM4(af[i][0], af[i][1], af[i][2], af[i][3], ad);
            }
#pragma unroll
            for (int jp = 0; jp < 4; jp++) {
                const uint32_t bd = sAs + boff[jp] + (uint32_t)((((c2 + cB) ^ xorL)) << 4);
                LDSM4(bf[2 * jp][0], bf[2 * jp][1], bf[2 * jp + 1][0], bf[2 * jp + 1][1], bd);
            }
#pragma unroll
            for (int i = 0; i < 4; i++)
#pragma unroll
                for (int j = 0; j < 8; j++)
                    MMA16816(acc[i][j], af[i], bf[j]);
        }
        if (++stage == 3) stage = 0;
    }

    // ---- epilogue ----
    const int rowBase = blockIdx.y * 128 + wm0 + g;
    const int colBase = blockIdx.x * 128 + wn0 + tig * 2;
    if (spl) {
        __half* sp = spl + (long long)z * sSpl;
#pragma unroll
        for (int i = 0; i < 4; i++)
#pragma unroll
            for (int rr = 0; rr < 2; rr++) {
                const int row = rowBase + i * 16 + rr * 8;
                __half* rp = sp + (long long)row * splPitch + splColOff;
#pragma unroll
                for (int j = 0; j < 8; j++) {
                    const int col = colBase + j * 8;
                    float v0 = acc[i][j][rr * 2], v1 = acc[i][j][rr * 2 + 1];
                    __half h0 = __float2half_rn(v0), h1 = __float2half_rn(v1);
                    __half l0 = __float2half_rn(v0 - __half2float(h0));
                    __half l1 = __float2half_rn(v1 - __half2float(h1));
                    __half2 ph; ph.x = h0; ph.y = h1;
                    __half2 pl; pl.x = l0; pl.y = l1;
                    *(__half2*)(rp + col)            = ph;
                    *(__half2*)(rp + splK + col)     = pl;
                    *(__half2*)(rp + 2 * splK + col) = ph;
                }
            }
    } else {
        float* Cb = C + (long long)z * sC;
#pragma unroll
        for (int i = 0; i < 4; i++)
#pragma unroll
            for (int rr = 0; rr < 2; rr++) {
                const int row = rowBase + i * 16 + rr * 8;
                float* rp = Cb + (long long)row * ldc;
#pragma unroll
                for (int j = 0; j < 8; j++) {
                    const int col = colBase + j * 8;
                    float v0 = acc[i][j][rr * 2], v1 = acc[i][j][rr * 2 + 1];
                    if (bias) { v0 += bias[col]; v1 += bias[col + 1]; }
                    if (relu) { v0 = fmaxf(v0, 0.f); v1 = fmaxf(v1, 0.f); }
                    float2 v; v.x = v0; v.y = v1;
                    *(float2*)(rp + col) = v;
                }
            }
    }
#undef LOAD_STAGE
}

// ---------------- prep / fused elementwise kernels ----------------------------

__device__ __forceinline__ void split2(float v, __half& hi, __half& lo) {
    hi = __float2half_rn(v);
    lo = __float2half_rn(v - __half2float(hi));
}

// weights: dst[R,3K] = [hi | hi | lo]
__global__ void k_prepW(const float* __restrict__ src, __half* __restrict__ dst,
                        int K, int total)
{
    int i = blockIdx.x * 256 + threadIdx.x;
    if (i >= total) return;
    int r = i / K, c = i - r * K;
    __half hi, lo; split2(src[i], hi, lo);
    __half* d = dst + (long long)r * 3 * K;
    d[c] = hi; d[K + c] = hi; d[2 * K + c] = lo;
}

// adjacency (0/1 exact): dst[b][r][c] = dst[b][r][256+c] = fp16(src)
__global__ void k_adjprep(const float* __restrict__ so, const float* __restrict__ si)
{
    int i = blockIdx.x * 256 + threadIdx.x;      // < 32*256*256
    int br = i >> 8, c = i & 255;
    __half vo = __float2half_rn(so[i]);
    __half vi = __float2half_rn(si[i]);
    g_adjO[(long long)br * 512 + c] = vo;  g_adjO[(long long)br * 512 + 256 + c] = vo;
    g_adjI[(long long)br * 512 + c] = vi;  g_adjI[(long long)br * 512 + 256 + c] = vi;
}

// h = annotation @ anno_W; also write split g_hp [hi|lo|hi]
__global__ void k_embed(const float* __restrict__ anno, const float* __restrict__ W)
{
    int r = blockIdx.x;
    __shared__ float arow[ANNO_];
    if (threadIdx.x < ANNO_) arow[threadIdx.x] = anno[r * ANNO_ + threadIdx.x];
    __syncthreads();
    for (int e = threadIdx.x; e < E_; e += blockDim.x) {
        float s = 0.f;
#pragma unroll
        for (int k = 0; k < ANNO_; k++) s = fmaf(arow[k], W[k * E_ + e], s);
        g_h[(long long)r * E_ + e] = s;
        __half hi, lo; split2(s, hi, lo);
        __half* hp = g_hp + (long long)r * 3072;
        hp[e] = hi; hp[1024 + e] = lo; hp[2048 + e] = hi;
    }
}

// per-batch transpose-split: g_ht[b][e][n]=hi(h[b][n][e]), [e][256+n]=lo
__global__ void k_transpose()
{
    __shared__ float t[32][33];
    int e0 = blockIdx.x * 32, n0 = blockIdx.y * 32, b = blockIdx.z;
    int tx = threadIdx.x, ty = threadIdx.y;   // 32 x 8
#pragma unroll
    for (int j = 0; j < 32; j += 8)
        t[ty + j][tx] = g_h[((long long)b * 256 + n0 + ty + j) * 1024 + e0 + tx];
    __syncthreads();
#pragma unroll
    for (int j = 0; j < 32; j += 8) {
        int e = e0 + ty + j;
        float v = t[tx][ty + j];
        __half hi, lo; split2(v, hi, lo);
        __half* rp = g_ht + ((long long)b * 1024 + e) * 512;
        rp[n0 + tx] = hi; rp[256 + n0 + tx] = lo;
    }
}

__device__ __forceinline__ float sigmoidf_(float x) { return 1.f / (1.f + expf(-x)); }

// encoder GRU update: g_h (f32, in place) + g_hp split
__global__ void k_gru()
{
    long long idx = (long long)blockIdx.x * 256 + threadIdx.x;  // r*1024 + e
    int r = (int)(idx >> 10);
    int e = (int)(idx & 1023);
    const float* gi = g_gi + (long long)r * 3072;
    const float* gh = g_gh + (long long)r * 3072;
    float rr = sigmoidf_(gi[e] + gh[e]);
    float zz = sigmoidf_(gi[1024 + e] + gh[1024 + e]);
    float nn = tanhf(gi[2048 + e] + rr * gh[2048 + e]);
    float hnew = (1.f - zz) * nn + zz * g_h[idx];
    g_h[idx] = hnew;
    __half hi, lo; split2(hnew, hi, lo);
    __half* hp = g_hp + (long long)r * 3072;
    hp[e] = hi; hp[1024 + e] = lo; hp[2048 + e] = hi;
}

__global__ void k_vnf(const float* __restrict__ vnow, const float* __restrict__ vall,
                      const float* __restrict__ Wn, const float* __restrict__ Wa)
{
    int b = blockIdx.x, d = threadIdx.x;
    float sn = 0.f, sa = 0.f;
#pragma unroll
    for (int k = 0; k < 16; k++) {
        sn = fmaf(vnow[b * 16 + k], Wn[k * 64 + d], sn);
        sa = fmaf(vall[b * 16 + k], Wa[k * 64 + d], sa);
    }
    g_vn[b * 64 + d] = sn;
    g_va[b * 64 + d] = sa;
}

// concat' = split([enc_out | npos | va | vn]) into g_cp [hi|lo|hi] pitch 3648
__global__ void k_concat(const int* __restrict__ from_node, const float* __restrict__ pos_enc)
{
    int r = blockIdx.x, b = r >> 8;
    __half* dst = g_cp + (long long)r * 3648;
    const float* hs = g_h + (long long)r * E_;
    for (int i = threadIdx.x; i < E_; i += blockDim.x) {
        __half hi, lo; split2(hs[i], hi, lo);
        dst[i] = hi; dst[1216 + i] = lo; dst[2432 + i] = hi;
    }
    int fn = from_node[b];
    for (int i = threadIdx.x; i < 64; i += blockDim.x) {
        float v0 = pos_enc[fn * 64 + i], v1 = g_va[b * 64 + i], v2 = g_vn[b * 64 + i];
        __half hi, lo;
        split2(v0, hi, lo); dst[1024 + i] = hi; dst[2240 + i] = lo; dst[3456 + i] = hi;
        split2(v1, hi, lo); dst[1088 + i] = hi; dst[2304 + i] = lo; dst[3520 + i] = hi;
        split2(v2, hi, lo); dst[1152 + i] = hi; dst[2368 + i] = lo; dst[3584 + i] = hi;
    }
}

// decoder GRU (h0=0 => gh=bhh): hidden f32 to d_out + split g_hidp
__global__ void k_decgru(const float* __restrict__ bhh, float* __restrict__ hidden_out)
{
    long long idx = (long long)blockIdx.x * 256 + threadIdx.x;  // r*2048 + e
    int r = (int)(idx >> 11);
    int e = (int)(idx & 2047);
    const float* gi = g_gid + (long long)r * 6144;
    float rr = sigmoidf_(gi[e] + bhh[e]);
    float zz = sigmoidf_(gi[2048 + e] + bhh[2048 + e]);
    float nn = tanhf(gi[4096 + e] + rr * bhh[4096 + e]);
    float hv = (1.f - zz) * nn;
    hidden_out[idx] = hv;
    __half hi, lo; split2(hv, hi, lo);
    __half* hp = g_hidp + (long long)r * 6144;
    hp[e] = hi; hp[2048 + e] = lo; hp[4096 + e] = hi;
}

// thin head: out3 = mid @ W2^T + b2
__global__ void k_out2(const float* __restrict__ W2, const float* __restrict__ b2)
{
    __shared__ float w[3][1024];
    int tid = threadIdx.x;
    for (int i = tid; i < 3 * 1024; i += 256) w[i >> 10][i & 1023] = W2[i];
    __syncthreads();
    int warp = tid >> 5, lane = tid & 31;
    int r = blockIdx.x * 8 + warp;
    const float* m = g_mid + (long long)r * 1024;
    float s0 = 0.f, s1 = 0.f, s2 = 0.f;
    for (int k = lane; k < 1024; k += 32) {
        float mv = m[k];
        s0 = fmaf(mv, w[0][k], s0);
        s1 = fmaf(mv, w[1][k], s1);
        s2 = fmaf(mv, w[2][k], s2);
    }
#pragma unroll
    for (int off = 16; off; off >>= 1) {
        s0 += __shfl_down_sync(0xffffffffu, s0, off);
        s1 += __shfl_down_sync(0xffffffffu, s1, off);
        s2 += __shfl_down_sync(0xffffffffu, s2, off);
    }
    if (lane == 0) {
        g_out3[r * 3 + 0] = s0 + b2[0];
        g_out3[r * 3 + 1] = s1 + b2[1];
        g_out3[r * 3 + 2] = s2 + b2[2];
    }
}

__global__ void k_max()
{
    int b = blockIdx.x;
    __shared__ float sm[256];
    float mx = -INFINITY;
    for (int i = threadIdx.x; i < N_ * AACT_; i += 256)
        mx = fmaxf(mx, g_out3[b * N_ * AACT_ + i]);
    sm[threadIdx.x] = mx;
    __syncthreads();
    for (int s = 128; s; s >>= 1) {
        if (threadIdx.x < s) sm[threadIdx.x] = fmaxf(sm[threadIdx.x], sm[threadIdx.x + s]);
        __syncthreads();
    }
    if (threadIdx.x == 0) g_maxv[b] = sm[0];
}

__global__ void k_final(const int* __restrict__ mask, float* __restrict__ out)
{
    int r = blockIdx.x * 256 + threadIdx.x;
    if (r >= BN_) return;
    int b = r >> 8;
    float mv = g_maxv[b] + 1.f;
    float mf = (mask[r] == 1) ? 1.f : 1e10f;
    out[r]                 = mf * (g_out3[r * 3 + 0] - mv) + 1.f;
    out[BN_ + r * 2 + 0]   = mf * (g_out3[r * 3 + 1] - mv) + 1.f;
    out[BN_ + r * 2 + 1]   = mf * (g_out3[r * 3 + 2] - mv) + 1.f;
}

// ---------------- launcher ----------------------------------------------------
extern "C" void kernel_launch(void* const* d_in, const int* in_sizes, int n_in,
                              void* d_out, int out_size)
{
    const float* annotation = (const float*)d_in[0];
    const float* A_out      = (const float*)d_in[1];
    const float* A_in       = (const float*)d_in[2];
    const int*   from_node  = (const int*)  d_in[3];
    const float* vnf_now    = (const float*)d_in[4];
    const float* vnf_all    = (const float*)d_in[5];
    const int*   mask       = (const int*)  d_in[6];
    const float* anno_W     = (const float*)d_in[7];
    const float* gru_Wih    = (const float*)d_in[8];
    const float* gru_Whh    = (const float*)d_in[9];
    const float* vnf_now_W  = (const float*)d_in[10];
    const float* vnf_all_W  = (const float*)d_in[11];
    const float* dgru_Wih   = (const float*)d_in[12];
    // d_in[13] = dgru_Whh: unused (h0 == 0 -> gh == dgru_bhh exactly)
    const float* dgru_bih   = (const float*)d_in[14];
    const float* dgru_bhh   = (const float*)d_in[15];
    const float* out_W1     = (const float*)d_in[16];
    const float* out_b1     = (const float*)d_in[17];
    const float* out_W2     = (const float*)d_in[18];
    const float* out_b2     = (const float*)d_in[19];
    const float* pos_enc    = (const float*)d_in[20];

    float* out = (float*)d_out;
    float* hidden = out + BN_ + BN_ * 2;

    cudaFuncSetAttribute(gemm_mma, cudaFuncAttributeMaxDynamicSharedMemorySize,
                         SMEM_TOTAL_GEMM);

    float *p_gi, *p_gh, *p_gid, *p_mid;
    __half *p_Wihp, *p_Whhp, *p_dWihp, *p_W1p, *p_adjO, *p_adjI;
    __half *p_ap, *p_hp, *p_ht, *p_cp, *p_hidp;
    cudaGetSymbolAddress((void**)&p_gi, g_gi);
    cudaGetSymbolAddress((void**)&p_gh, g_gh);
    cudaGetSymbolAddress((void**)&p_gid, g_gid);
    cudaGetSymbolAddress((void**)&p_mid, g_mid);
    cudaGetSymbolAddress((void**)&p_Wihp, g_Wihp);
    cudaGetSymbolAddress((void**)&p_Whhp, g_Whhp);
    cudaGetSymbolAddress((void**)&p_dWihp, g_dWihp);
    cudaGetSymbolAddress((void**)&p_W1p, g_W1p);
    cudaGetSymbolAddress((void**)&p_adjO, g_adjO);
    cudaGetSymbolAddress((void**)&p_adjI, g_adjI);
    cudaGetSymbolAddress((void**)&p_ap, g_ap);
    cudaGetSymbolAddress((void**)&p_hp, g_hp);
    cudaGetSymbolAddress((void**)&p_ht, g_ht);
    cudaGetSymbolAddress((void**)&p_cp, g_cp);
    cudaGetSymbolAddress((void**)&p_hidp, g_hidp);

    // ---- prep: weight splits, adjacency, embedding ----
    k_prepW<<<(3072 * 2048 + 255) / 256, 256>>>(gru_Wih, p_Wihp, 2048, 3072 * 2048);
    k_prepW<<<(3072 * 1024 + 255) / 256, 256>>>(gru_Whh, p_Whhp, 1024, 3072 * 1024);
    k_prepW<<<(6144 * 1216 + 255) / 256, 256>>>(dgru_Wih, p_dWihp, 1216, 6144 * 1216);
    k_prepW<<<(1024 * 2048 + 255) / 256, 256>>>(out_W1, p_W1p, 2048, 1024 * 2048);
    k_adjprep<<<(B_ * 256 * 256) / 256, 256>>>(A_out, A_in);
    k_embed<<<BN_, 256>>>(annotation, anno_W);

    // ---- T encoder GRU steps ----
    for (int t = 0; t < T_; t++) {
        k_transpose<<<dim3(32, 8, 32), dim3(32, 8)>>>();
        // a_out/a_in = Adj @ h  -> split directly into g_ap ([hi|lo|hi], K'=6144)
        gemm_mma<<<dim3(8, 2, 32), 128, SMEM_TOTAL_GEMM>>>(
            p_adjO, p_ht, 512, 256LL * 512, 1024LL * 512,
            nullptr, 0, 0, nullptr, 0,
            p_ap, 6144, 2048, 0, 256LL * 6144);
        gemm_mma<<<dim3(8, 2, 32), 128, SMEM_TOTAL_GEMM>>>(
            p_adjI, p_ht, 512, 256LL * 512, 1024LL * 512,
            nullptr, 0, 0, nullptr, 0,
            p_ap, 6144, 2048, 1024, 256LL * 6144);
        // gi = a' @ Wih'^T   [8192,3072] K'=6144
        gemm_mma<<<dim3(24, 64, 1), 128, SMEM_TOTAL_GEMM>>>(
            p_ap, p_Wihp, 6144, 0, 0,
            p_gi, 3072, 0, nullptr, 0, nullptr, 0, 0, 0, 0);
        // gh = h' @ Whh'^T   [8192,3072] K'=3072
        gemm_mma<<<dim3(24, 64, 1), 128, SMEM_TOTAL_GEMM>>>(
            p_hp, p_Whhp, 3072, 0, 0,
            p_gh, 3072, 0, nullptr, 0, nullptr, 0, 0, 0, 0);
        k_gru<<<BN_ * E_ / 256, 256>>>();
    }

    // ---- decoder ----
    k_vnf<<<B_, 64>>>(vnf_now, vnf_all, vnf_now_W, vnf_all_W);
    k_concat<<<BN_, 256>>>(from_node, pos_enc);
    // gi_dec = concat' @ dWih'^T + bih   [8192,6144] K'=3648
    gemm_mma<<<dim3(48, 64, 1), 128, SMEM_TOTAL_GEMM>>>(
        p_cp, p_dWihp, 3648, 0, 0,
        p_gid, 6144, 0, dgru_bih, 0, nullptr, 0, 0, 0, 0);
    k_decgru<<<BN_ * 2 * E_ / 256, 256>>>(dgru_bhh, hidden);
    // mid = relu(hidden' @ W1'^T + b1)   [8192,1024] K'=6144
    gemm_mma<<<dim3(8, 64, 1), 128, SMEM_TOTAL_GEMM>>>(
        p_hidp, p_W1p, 6144, 0, 0,
        p_mid, 1024, 0, out_b1, 1, nullptr, 0, 0, 0, 0);

    // ---- head ----
    k_out2<<<BN_ / 8, 256>>>(out_W2, out_b2);
    k_max<<<B_, 256>>>();
    k_final<<<BN_ / 256, 256>>>(mask, out);
}

// round 11
// speedup vs baseline: 1.0652x; 1.0652x over previous
#include <cuda_runtime.h>
#include <cuda_fp16.h>
#include <math.h>
#include <stdint.h>

// Problem constants
#define B_    32
#define N_    256
#define E_    1024
#define T_    5
#define ANNO_ 18
#define AACT_ 3
#define BN_   8192
#define DEC_IN_ 1216   // E + ND + 2*VD

// ---------------- scratch (static device globals; no allocation) -------------
__device__ __align__(256) float g_h  [BN_ * E_];
__device__ __align__(256) float g_gi [BN_ * 3 * E_];
__device__ __align__(256) float g_gh [BN_ * 3 * E_];
__device__ __align__(256) float g_gid[BN_ * 6 * E_];
__device__ __align__(256) float g_mid[BN_ * E_];
__device__ __align__(256) float g_out3[BN_ * AACT_];
__device__ float g_vn[B_ * 64];
__device__ float g_va[B_ * 64];
__device__ float g_maxv[B_];

// fp16 3-term split operands (merged-K layouts)
// weights: [hi|hi|lo]   activations: [hi|lo|hi]
// => A_hi*W_hi + A_lo*W_hi + A_hi*W_lo  (residual ~2^-22)
__device__ __align__(256) __half g_Wihp [3072 * 6144];
__device__ __align__(256) __half g_Whhp [3072 * 3072];
__device__ __align__(256) __half g_dWihp[6144 * 3648];
__device__ __align__(256) __half g_W1p  [1024 * 6144];
__device__ __align__(256) __half g_adjO [B_ * 256 * 512];
__device__ __align__(256) __half g_adjI [B_ * 256 * 512];
__device__ __align__(256) __half g_ap   [BN_ * 6144];
__device__ __align__(256) __half g_hp   [BN_ * 3072];
__device__ __align__(256) __half g_ht   [B_ * 1024 * 512];
__device__ __align__(256) __half g_cp   [BN_ * 3648];
__device__ __align__(256) __half g_hidp [BN_ * 6144];

// ---------------- helpers -----------------------------------------------------
__device__ __forceinline__ uint32_t s2u(const void* p) {
    uint32_t a;
    asm("{ .reg .u64 t; cvta.to.shared.u64 t, %1; cvt.u32.u64 %0, t; }" : "=r"(a) : "l"(p));
    return a;
}
__device__ __forceinline__ uint64_t g2u(const void* p) {
    uint64_t a;
    asm("cvta.to.global.u64 %0, %1;" : "=l"(a) : "l"(p));
    return a;
}

#define CP_ASYNC16(smem_u32, gptr64) \
    asm volatile("cp.async.cg.shared.global [%0], [%1], 16;" :: "r"(smem_u32), "l"(gptr64))
#define CP_COMMIT() asm volatile("cp.async.commit_group;" ::: "memory")
#define CP_WAIT(n)  asm volatile("cp.async.wait_group %0;" :: "n"(n) : "memory")

#define LDSM4(r0, r1, r2, r3, addr)                                           \
    asm volatile("ldmatrix.sync.aligned.m8n8.x4.shared.b16 {%0,%1,%2,%3}, [%4];" \
                 : "=r"(r0), "=r"(r1), "=r"(r2), "=r"(r3) : "r"(addr))

#define MMA16816(d, a, b)                                                     \
    asm volatile(                                                             \
        "mma.sync.aligned.m16n8k16.row.col.f32.f16.f16.f32 "                  \
        "{%0,%1,%2,%3}, {%4,%5,%6,%7}, {%8,%9}, {%0,%1,%2,%3};"               \
        : "+f"((d)[0]), "+f"((d)[1]), "+f"((d)[2]), "+f"((d)[3])              \
        : "r"((a)[0]), "r"((a)[1]), "r"((a)[2]), "r"((a)[3]),                 \
          "r"((b)[0]), "r"((b)[1]))

// ---------------- mma.sync GEMM: C[M,N] = A[M,K'] * B[N,K']^T -----------------
// Round-8 topology: CTA 128x128, BK=64, 8 warps (warp 64x32), 256 threads,
// XOR-swizzled SMEM + ldmatrix.x4, 3-stage cp.async, 96KB smem, 2 CTA/SM.
#define STAGE_BYTES 32768      // A 16KB + B 16KB
#define B_OFF       16384
#define SMEM_TOTAL_GEMM (3 * STAGE_BYTES)

__global__ __launch_bounds__(256, 2)
void gemm_mma(const __half* __restrict__ A, const __half* __restrict__ Bm,
              int Kp, long long sA, long long sB,
              float* __restrict__ C, int ldc, long long sC,
              const float* __restrict__ bias, int relu,
              __half* __restrict__ spl, int splPitch, int splK, int splColOff,
              long long sSpl)
{
    extern __shared__ char smem[];
    const uint32_t smb = s2u(smem);

    const int tid  = threadIdx.x;
    const int wid  = tid >> 5, lane = tid & 31;
    const int g    = lane >> 2, tig = lane & 3;
    const int wm0  = (wid & 1) * 64;
    const int wn0  = (wid >> 1) * 32;
    const int z    = blockIdx.z;

    const __half* Ab = A  + (long long)z * sA + (long long)(blockIdx.y * 128) * Kp;
    const __half* Bb = Bm + (long long)z * sB + (long long)(blockIdx.x * 128) * Kp;

    // cp.async coords: 1024 16B chunks per operand per stage, 4/thread
    const int rbase = tid >> 3;            // 0..31
    const int ch    = tid & 7;
    uint64_t gA[4], gB[4];
    uint32_t sAo[4], sBo[4];
#pragma unroll
    for (int i = 0; i < 4; i++) {
        const int r = rbase + 32 * i;
        gA[i] = g2u((const char*)Ab + (long long)r * (Kp * 2) + ch * 16);
        gB[i] = g2u((const char*)Bb + (long long)r * (Kp * 2) + ch * 16);
        const uint32_t sw = (uint32_t)((ch ^ (r & 7)) << 4);
        sAo[i] = smb + r * 128 + sw;
        sBo[i] = smb + B_OFF + r * 128 + sw;
    }

#define LOAD_STAGE(s, idx)                                                 \
    do {                                                                   \
        const long long kB = (long long)(idx) * 128;                       \
        const uint32_t so = (uint32_t)(s) * STAGE_BYTES;                   \
        CP_ASYNC16(sAo[0] + so, gA[0] + kB);                               \
        CP_ASYNC16(sAo[1] + so, gA[1] + kB);                               \
        CP_ASYNC16(sAo[2] + so, gA[2] + kB);                               \
        CP_ASYNC16(sAo[3] + so, gA[3] + kB);                               \
        CP_ASYNC16(sBo[0] + so, gB[0] + kB);                               \
        CP_ASYNC16(sBo[1] + so, gB[1] + kB);                               \
        CP_ASYNC16(sBo[2] + so, gB[2] + kB);                               \
        CP_ASYNC16(sBo[3] + so, gB[3] + kB);                               \
    } while (0)

    const int xorL = lane & 7;
    const int cA   = lane >> 4;
    const int cB   = (lane >> 3) & 1;
    uint32_t aoff[4], boff[2];
#pragma unroll
    for (int i = 0; i < 4; i++)
        aoff[i] = (uint32_t)(wm0 + i * 16 + (lane & 15)) * 128;
#pragma unroll
    for (int jp = 0; jp < 2; jp++)
        boff[jp] = (uint32_t)(wn0 + jp * 16 + (lane & 7) + ((lane & 16) >> 1)) * 128 + B_OFF;

    float acc[4][4][4];
#pragma unroll
    for (int i = 0; i < 4; i++)
#pragma unroll
        for (int j = 0; j < 4; j++)
#pragma unroll
            for (int c = 0; c < 4; c++) acc[i][j][c] = 0.f;

    const int nIter = Kp >> 6;

    LOAD_STAGE(0, 0); CP_COMMIT();
    if (nIter > 1) LOAD_STAGE(1, 1);
    CP_COMMIT();

    int stage = 0;
    for (int it = 0; it < nIter; ++it) {
        CP_WAIT(1);
        __syncthreads();

        if (it + 2 < nIter) {
            int ns = stage + 2; if (ns >= 3) ns -= 3;
            LOAD_STAGE(ns, it + 2);
        }
        CP_COMMIT();

        const uint32_t sAs = smb + stage * STAGE_BYTES;
#pragma unroll
        for (int ks = 0; ks < 4; ks++) {
            const int c2 = ks * 2;
            uint32_t af[4][4], bf[4][2];
#pragma unroll
            for (int i = 0; i < 4; i++) {
                const uint32_t ad = sAs + aoff[i] + (uint32_t)((((c2 + cA) ^ xorL)) << 4);
                LDSM4(af[i][0], af[i][1], af[i][2], af[i][3], ad);
            }
#pragma unroll
            for (int jp = 0; jp < 2; jp++) {
                const uint32_t bd = sAs + boff[jp] + (uint32_t)((((c2 + cB) ^ xorL)) << 4);
                LDSM4(bf[2 * jp][0], bf[2 * jp][1], bf[2 * jp + 1][0], bf[2 * jp + 1][1], bd);
            }
#pragma unroll
            for (int i = 0; i < 4; i++)
#pragma unroll
                for (int j = 0; j < 4; j++)
                    MMA16816(acc[i][j], af[i], bf[j]);
        }
        if (++stage == 3) stage = 0;
    }

    // ---- epilogue ----
    const int rowBase = blockIdx.y * 128 + wm0 + g;
    const int colBase = blockIdx.x * 128 + wn0 + tig * 2;
    if (spl) {
        __half* sp = spl + (long long)z * sSpl;
#pragma unroll
        for (int i = 0; i < 4; i++)
#pragma unroll
            for (int rr = 0; rr < 2; rr++) {
                const int row = rowBase + i * 16 + rr * 8;
                __half* rp = sp + (long long)row * splPitch + splColOff;
#pragma unroll
                for (int j = 0; j < 4; j++) {
                    const int col = colBase + j * 8;
                    float v0 = acc[i][j][rr * 2], v1 = acc[i][j][rr * 2 + 1];
                    __half h0 = __float2half_rn(v0), h1 = __float2half_rn(v1);
                    __half l0 = __float2half_rn(v0 - __half2float(h0));
                    __half l1 = __float2half_rn(v1 - __half2float(h1));
                    __half2 ph; ph.x = h0; ph.y = h1;
                    __half2 pl; pl.x = l0; pl.y = l1;
                    *(__half2*)(rp + col)            = ph;
                    *(__half2*)(rp + splK + col)     = pl;
                    *(__half2*)(rp + 2 * splK + col) = ph;
                }
            }
    } else {
        float* Cb = C + (long long)z * sC;
#pragma unroll
        for (int i = 0; i < 4; i++)
#pragma unroll
            for (int rr = 0; rr < 2; rr++) {
                const int row = rowBase + i * 16 + rr * 8;
                float* rp = Cb + (long long)row * ldc;
#pragma unroll
                for (int j = 0; j < 4; j++) {
                    const int col = colBase + j * 8;
                    float v0 = acc[i][j][rr * 2], v1 = acc[i][j][rr * 2 + 1];
                    if (bias) { v0 += bias[col]; v1 += bias[col + 1]; }
                    if (relu) { v0 = fmaxf(v0, 0.f); v1 = fmaxf(v1, 0.f); }
                    float2 v; v.x = v0; v.y = v1;
                    *(float2*)(rp + col) = v;
                }
            }
    }
#undef LOAD_STAGE
}

// ---------------- prep / fused elementwise kernels ----------------------------

__device__ __forceinline__ void split2(float v, __half& hi, __half& lo) {
    hi = __float2half_rn(v);
    lo = __float2half_rn(v - __half2float(hi));
}
__device__ __forceinline__ __half2 mkh2(__half a, __half b) {
    __half2 r; r.x = a; r.y = b; return r;
}

// weights: dst[R,3K] = [hi | hi | lo]
__global__ void k_prepW(const float* __restrict__ src, __half* __restrict__ dst,
                        int K, int total)
{
    int i = blockIdx.x * 256 + threadIdx.x;
    if (i >= total) return;
    int r = i / K, c = i - r * K;
    __half hi, lo; split2(src[i], hi, lo);
    __half* d = dst + (long long)r * 3 * K;
    d[c] = hi; d[K + c] = hi; d[2 * K + c] = lo;
}

// adjacency (0/1 exact): dst[b][r][c] = dst[b][r][256+c] = fp16(src)
__global__ void k_adjprep(const float* __restrict__ so, const float* __restrict__ si)
{
    int i = blockIdx.x * 256 + threadIdx.x;
    int br = i >> 8, c = i & 255;
    __half vo = __float2half_rn(so[i]);
    __half vi = __float2half_rn(si[i]);
    g_adjO[(long long)br * 512 + c] = vo;  g_adjO[(long long)br * 512 + 256 + c] = vo;
    g_adjI[(long long)br * 512 + c] = vi;  g_adjI[(long long)br * 512 + 256 + c] = vi;
}

// h = annotation @ anno_W (4 cols/thread); split g_hp [hi|lo|hi]
__global__ void k_embed(const float* __restrict__ anno, const float* __restrict__ W)
{
    int r = blockIdx.x;
    __shared__ float arow[ANNO_];
    if (threadIdx.x < ANNO_) arow[threadIdx.x] = anno[r * ANNO_ + threadIdx.x];
    __syncthreads();
    int e = threadIdx.x * 4;   // 256 threads * 4 = 1024
    float s[4] = {0.f, 0.f, 0.f, 0.f};
#pragma unroll
    for (int k = 0; k < ANNO_; k++) {
        float a = arow[k];
        float4 wv = *(const float4*)(W + k * E_ + e);
        s[0] = fmaf(a, wv.x, s[0]); s[1] = fmaf(a, wv.y, s[1]);
        s[2] = fmaf(a, wv.z, s[2]); s[3] = fmaf(a, wv.w, s[3]);
    }
    float4 hv; hv.x = s[0]; hv.y = s[1]; hv.z = s[2]; hv.w = s[3];
    *(float4*)(g_h + (long long)r * E_ + e) = hv;
    __half hi[4], lo[4];
#pragma unroll
    for (int c = 0; c < 4; c++) split2(s[c], hi[c], lo[c]);
    __half* hp = g_hp + (long long)r * 3072 + e;
    *(__half2*)(hp)          = mkh2(hi[0], hi[1]); *(__half2*)(hp + 2)        = mkh2(hi[2], hi[3]);
    *(__half2*)(hp + 1024)   = mkh2(lo[0], lo[1]); *(__half2*)(hp + 1026)     = mkh2(lo[2], lo[3]);
    *(__half2*)(hp + 2048)   = mkh2(hi[0], hi[1]); *(__half2*)(hp + 2050)     = mkh2(hi[2], hi[3]);
}

// per-batch transpose-split: g_ht[b][e][n]=hi(h[b][n][e]), [e][256+n]=lo
__global__ void k_transpose()
{
    __shared__ float t[32][33];
    int e0 = blockIdx.x * 32, n0 = blockIdx.y * 32, b = blockIdx.z;
    int tx = threadIdx.x, ty = threadIdx.y;   // 32 x 8
#pragma unroll
    for (int j = 0; j < 32; j += 8)
        t[ty + j][tx] = g_h[((long long)b * 256 + n0 + ty + j) * 1024 + e0 + tx];
    __syncthreads();
    if (tx < 16) {
#pragma unroll
        for (int j = 0; j < 32; j += 8) {
            int e = e0 + ty + j;
            float v0 = t[2 * tx][ty + j];
            float v1 = t[2 * tx + 1][ty + j];
            __half h0, l0, h1, l1;
            split2(v0, h0, l0); split2(v1, h1, l1);
            __half* rp = g_ht + ((long long)b * 1024 + e) * 512;
            *(__half2*)(rp + n0 + 2 * tx)       = mkh2(h0, h1);
            *(__half2*)(rp + 256 + n0 + 2 * tx) = mkh2(l0, l1);
        }
    }
}

__device__ __forceinline__ float sigmoidf_(float x) { return 1.f / (1.f + expf(-x)); }

// encoder GRU update, 4 elems/thread: g_h (f32, in place) + g_hp split
__global__ void k_gru()
{
    long long idx = ((long long)blockIdx.x * 256 + threadIdx.x) * 4;  // r*1024 + e
    int r = (int)(idx >> 10);
    int e = (int)(idx & 1023);
    const float* gi = g_gi + (long long)r * 3072 + e;
    const float* gh = g_gh + (long long)r * 3072 + e;
    float4 gir = *(const float4*)gi;
    float4 giz = *(const float4*)(gi + 1024);
    float4 gin = *(const float4*)(gi + 2048);
    float4 ghr = *(const float4*)gh;
    float4 ghz = *(const float4*)(gh + 1024);
    float4 ghn = *(const float4*)(gh + 2048);
    float4 hv  = *(const float4*)(g_h + idx);
    float hn[4];
    {
        const float* pir = &gir.x; const float* piz = &giz.x; const float* pin = &gin.x;
        const float* phr = &ghr.x; const float* phz = &ghz.x; const float* phn = &ghn.x;
        const float* ph  = &hv.x;
#pragma unroll
        for (int c = 0; c < 4; c++) {
            float rr = sigmoidf_(pir[c] + phr[c]);
            float zz = sigmoidf_(piz[c] + phz[c]);
            float nn = tanhf(pin[c] + rr * phn[c]);
            hn[c] = (1.f - zz) * nn + zz * ph[c];
        }
    }
    float4 ho; ho.x = hn[0]; ho.y = hn[1]; ho.z = hn[2]; ho.w = hn[3];
    *(float4*)(g_h + idx) = ho;
    __half hi[4], lo[4];
#pragma unroll
    for (int c = 0; c < 4; c++) split2(hn[c], hi[c], lo[c]);
    __half* hp = g_hp + (long long)r * 3072 + e;
    *(__half2*)(hp)        = mkh2(hi[0], hi[1]); *(__half2*)(hp + 2)      = mkh2(hi[2], hi[3]);
    *(__half2*)(hp + 1024) = mkh2(lo[0], lo[1]); *(__half2*)(hp + 1026)   = mkh2(lo[2], lo[3]);
    *(__half2*)(hp + 2048) = mkh2(hi[0], hi[1]); *(__half2*)(hp + 2050)   = mkh2(hi[2], hi[3]);
}

__global__ void k_vnf(const float* __restrict__ vnow, const float* __restrict__ vall,
                      const float* __restrict__ Wn, const float* __restrict__ Wa)
{
    int b = blockIdx.x, d = threadIdx.x;
    float sn = 0.f, sa = 0.f;
#pragma unroll
    for (int k = 0; k < 16; k++) {
        sn = fmaf(vnow[b * 16 + k], Wn[k * 64 + d], sn);
        sa = fmaf(vall[b * 16 + k], Wa[k * 64 + d], sa);
    }
    g_vn[b * 64 + d] = sn;
    g_va[b * 64 + d] = sa;
}

// concat' = split([enc_out | npos | va | vn]) into g_cp [hi|lo|hi] pitch 3648
__global__ void k_concat(const int* __restrict__ from_node, const float* __restrict__ pos_enc)
{
    int r = blockIdx.x, b = r >> 8;
    __half* dst = g_cp + (long long)r * 3648;
    const float* hs = g_h + (long long)r * E_;
    {
        int i = threadIdx.x * 4;   // 256 threads * 4 = 1024
        float4 v = *(const float4*)(hs + i);
        __half hi[4], lo[4];
        split2(v.x, hi[0], lo[0]); split2(v.y, hi[1], lo[1]);
        split2(v.z, hi[2], lo[2]); split2(v.w, hi[3], lo[3]);
        *(__half2*)(dst + i)            = mkh2(hi[0], hi[1]); *(__half2*)(dst + i + 2)        = mkh2(hi[2], hi[3]);
        *(__half2*)(dst + 1216 + i)     = mkh2(lo[0], lo[1]); *(__half2*)(dst + 1216 + i + 2) = mkh2(lo[2], lo[3]);
        *(__half2*)(dst + 2432 + i)     = mkh2(hi[0], hi[1]); *(__half2*)(dst + 2432 + i + 2) = mkh2(hi[2], hi[3]);
    }
    int fn = from_node[b];
    for (int i = threadIdx.x; i < 64; i += blockDim.x) {
        float v0 = pos_enc[fn * 64 + i], v1 = g_va[b * 64 + i], v2 = g_vn[b * 64 + i];
        __half hi, lo;
        split2(v0, hi, lo); dst[1024 + i] = hi; dst[2240 + i] = lo; dst[3456 + i] = hi;
        split2(v1, hi, lo); dst[1088 + i] = hi; dst[2304 + i] = lo; dst[3520 + i] = hi;
        split2(v2, hi, lo); dst[1152 + i] = hi; dst[2368 + i] = lo; dst[3584 + i] = hi;
    }
}

// decoder GRU (h0=0 => gh=bhh), 4 elems/thread
__global__ void k_decgru(const float* __restrict__ bhh, float* __restrict__ hidden_out)
{
    long long idx = ((long long)blockIdx.x * 256 + threadIdx.x) * 4;  // r*2048 + e
    int r = (int)(idx >> 11);
    int e = (int)(idx & 2047);
    const float* gi = g_gid + (long long)r * 6144 + e;
    float4 gir = *(const float4*)gi;
    float4 giz = *(const float4*)(gi + 2048);
    float4 gin = *(const float4*)(gi + 4096);
    float4 bhr = *(const float4*)(bhh + e);
    float4 bhz = *(const float4*)(bhh + 2048 + e);
    float4 bhn = *(const float4*)(bhh + 4096 + e);
    float hv[4];
    {
        const float* pir = &gir.x; const float* piz = &giz.x; const float* pin = &gin.x;
        const float* pbr = &bhr.x; const float* pbz = &bhz.x; const float* pbn = &bhn.x;
#pragma unroll
        for (int c = 0; c < 4; c++) {
            float rr = sigmoidf_(pir[c] + pbr[c]);
            float zz = sigmoidf_(piz[c] + pbz[c]);
            float nn = tanhf(pin[c] + rr * pbn[c]);
            hv[c] = (1.f - zz) * nn;
        }
    }
    float4 ho; ho.x = hv[0]; ho.y = hv[1]; ho.z = hv[2]; ho.w = hv[3];
    *(float4*)(hidden_out + idx) = ho;
    __half hi[4], lo[4];
#pragma unroll
    for (int c = 0; c < 4; c++) split2(hv[c], hi[c], lo[c]);
    __half* hp = g_hidp + (long long)r * 6144 + e;
    *(__half2*)(hp)        = mkh2(hi[0], hi[1]); *(__half2*)(hp + 2)      = mkh2(hi[2], hi[3]);
    *(__half2*)(hp + 2048) = mkh2(lo[0], lo[1]); *(__half2*)(hp + 2050)   = mkh2(lo[2], lo[3]);
    *(__half2*)(hp + 4096) = mkh2(hi[0], hi[1]); *(__half2*)(hp + 4098)   = mkh2(hi[2], hi[3]);
}

// thin head: out3 = mid @ W2^T + b2
__global__ void k_out2(const float* __restrict__ W2, const float* __restrict__ b2)
{
    __shared__ float w[3][1024];
    int tid = threadIdx.x;
    for (int i = tid; i < 3 * 1024; i += 256) w[i >> 10][i & 1023] = W2[i];
    __syncthreads();
    int warp = tid >> 5, lane = tid & 31;
    int r = blockIdx.x * 8 + warp;
    const float* m = g_mid + (long long)r * 1024;
    float s0 = 0.f, s1 = 0.f, s2 = 0.f;
    for (int k = lane; k < 1024; k += 32) {
        float mv = m[k];
        s0 = fmaf(mv, w[0][k], s0);
        s1 = fmaf(mv, w[1][k], s1);
        s2 = fmaf(mv, w[2][k], s2);
    }
#pragma unroll
    for (int off = 16; off; off >>= 1) {
        s0 += __shfl_down_sync(0xffffffffu, s0, off);
        s1 += __shfl_down_sync(0xffffffffu, s1, off);
        s2 += __shfl_down_sync(0xffffffffu, s2, off);
    }
    if (lane == 0) {
        g_out3[r * 3 + 0] = s0 + b2[0];
        g_out3[r * 3 + 1] = s1 + b2[1];
        g_out3[r * 3 + 2] = s2 + b2[2];
    }
}

__global__ void k_max()
{
    int b = blockIdx.x;
    __shared__ float sm[256];
    float mx = -INFINITY;
    for (int i = threadIdx.x; i < N_ * AACT_; i += 256)
        mx = fmaxf(mx, g_out3[b * N_ * AACT_ + i]);
    sm[threadIdx.x] = mx;
    __syncthreads();
    for (int s = 128; s; s >>= 1) {
        if (threadIdx.x < s) sm[threadIdx.x] = fmaxf(sm[threadIdx.x], sm[threadIdx.x + s]);
        __syncthreads();
    }
    if (threadIdx.x == 0) g_maxv[b] = sm[0];
}

__global__ void k_final(const int* __restrict__ mask, float* __restrict__ out)
{
    int r = blockIdx.x * 256 + threadIdx.x;
    if (r >= BN_) return;
    int b = r >> 8;
    float mv = g_maxv[b] + 1.f;
    float mf = (mask[r] == 1) ? 1.f : 1e10f;
    out[r]                 = mf * (g_out3[r * 3 + 0] - mv) + 1.f;
    out[BN_ + r * 2 + 0]   = mf * (g_out3[r * 3 + 1] - mv) + 1.f;
    out[BN_ + r * 2 + 1]   = mf * (g_out3[r * 3 + 2] - mv) + 1.f;
}

// ---------------- launcher ----------------------------------------------------
extern "C" void kernel_launch(void* const* d_in, const int* in_sizes, int n_in,
                              void* d_out, int out_size)
{
    const float* annotation = (const float*)d_in[0];
    const float* A_out      = (const float*)d_in[1];
    const float* A_in       = (const float*)d_in[2];
    const int*   from_node  = (const int*)  d_in[3];
    const float* vnf_now    = (const float*)d_in[4];
    const float* vnf_all    = (const float*)d_in[5];
    const int*   mask       = (const int*)  d_in[6];
    const float* anno_W     = (const float*)d_in[7];
    const float* gru_Wih    = (const float*)d_in[8];
    const float* gru_Whh    = (const float*)d_in[9];
    const float* vnf_now_W  = (const float*)d_in[10];
    const float* vnf_all_W  = (const float*)d_in[11];
    const float* dgru_Wih   = (const float*)d_in[12];
    // d_in[13] = dgru_Whh: unused (h0 == 0 -> gh == dgru_bhh exactly)
    const float* dgru_bih   = (const float*)d_in[14];
    const float* dgru_bhh   = (const float*)d_in[15];
    const float* out_W1     = (const float*)d_in[16];
    const float* out_b1     = (const float*)d_in[17];
    const float* out_W2     = (const float*)d_in[18];
    const float* out_b2     = (const float*)d_in[19];
    const float* pos_enc    = (const float*)d_in[20];

    float* out = (float*)d_out;
    float* hidden = out + BN_ + BN_ * 2;

    cudaFuncSetAttribute(gemm_mma, cudaFuncAttributeMaxDynamicSharedMemorySize,
                         SMEM_TOTAL_GEMM);

    float *p_gi, *p_gh, *p_gid, *p_mid;
    __half *p_Wihp, *p_Whhp, *p_dWihp, *p_W1p, *p_adjO, *p_adjI;
    __half *p_ap, *p_hp, *p_ht, *p_cp, *p_hidp;
    cudaGetSymbolAddress((void**)&p_gi, g_gi);
    cudaGetSymbolAddress((void**)&p_gh, g_gh);
    cudaGetSymbolAddress((void**)&p_gid, g_gid);
    cudaGetSymbolAddress((void**)&p_mid, g_mid);
    cudaGetSymbolAddress((void**)&p_Wihp, g_Wihp);
    cudaGetSymbolAddress((void**)&p_Whhp, g_Whhp);
    cudaGetSymbolAddress((void**)&p_dWihp, g_dWihp);
    cudaGetSymbolAddress((void**)&p_W1p, g_W1p);
    cudaGetSymbolAddress((void**)&p_adjO, g_adjO);
    cudaGetSymbolAddress((void**)&p_adjI, g_adjI);
    cudaGetSymbolAddress((void**)&p_ap, g_ap);
    cudaGetSymbolAddress((void**)&p_hp, g_hp);
    cudaGetSymbolAddress((void**)&p_ht, g_ht);
    cudaGetSymbolAddress((void**)&p_cp, g_cp);
    cudaGetSymbolAddress((void**)&p_hidp, g_hidp);

    // ---- prep needed for encoder only (decoder prep deferred) ----
    // Launch order puts a gemm_mma at slot 5 for ncu (-s 5 -c 1).
    k_prepW<<<(3072 * 2048 + 255) / 256, 256>>>(gru_Wih, p_Wihp, 2048, 3072 * 2048);   // 0
    k_prepW<<<(3072 * 1024 + 255) / 256, 256>>>(gru_Whh, p_Whhp, 1024, 3072 * 1024);   // 1
    k_adjprep<<<(B_ * 256 * 256) / 256, 256>>>(A_out, A_in);                            // 2
    k_embed<<<BN_, 256>>>(annotation, anno_W);                                          // 3

    // ---- T encoder GRU steps ----
    for (int t = 0; t < T_; t++) {
        k_transpose<<<dim3(32, 8, 32), dim3(32, 8)>>>();                                // 4
        gemm_mma<<<dim3(8, 2, 32), 256, SMEM_TOTAL_GEMM>>>(                             // 5 <- ncu
            p_adjO, p_ht, 512, 256LL * 512, 1024LL * 512,
            nullptr, 0, 0, nullptr, 0,
            p_ap, 6144, 2048, 0, 256LL * 6144);
        gemm_mma<<<dim3(8, 2, 32), 256, SMEM_TOTAL_GEMM>>>(
            p_adjI, p_ht, 512, 256LL * 512, 1024LL * 512,
            nullptr, 0, 0, nullptr, 0,
            p_ap, 6144, 2048, 1024, 256LL * 6144);
        // gi = a' @ Wih'^T   [8192,3072] K'=6144
        gemm_mma<<<dim3(24, 64, 1), 256, SMEM_TOTAL_GEMM>>>(
            p_ap, p_Wihp, 6144, 0, 0,
            p_gi, 3072, 0, nullptr, 0, nullptr, 0, 0, 0, 0);
        // gh = h' @ Whh'^T   [8192,3072] K'=3072
        gemm_mma<<<dim3(24, 64, 1), 256, SMEM_TOTAL_GEMM>>>(
            p_hp, p_Whhp, 3072, 0, 0,
            p_gh, 3072, 0, nullptr, 0, nullptr, 0, 0, 0, 0);
        k_gru<<<BN_ * E_ / 1024, 256>>>();
    }

    // ---- decoder prep + decoder ----
    k_prepW<<<(6144 * 1216 + 255) / 256, 256>>>(dgru_Wih, p_dWihp, 1216, 6144 * 1216);
    k_prepW<<<(1024 * 2048 + 255) / 256, 256>>>(out_W1, p_W1p, 2048, 1024 * 2048);
    k_vnf<<<B_, 64>>>(vnf_now, vnf_all, vnf_now_W, vnf_all_W);
    k_concat<<<BN_, 256>>>(from_node, pos_enc);
    // gi_dec = concat' @ dWih'^T + bih   [8192,6144] K'=3648
    gemm_mma<<<dim3(48, 64, 1), 256, SMEM_TOTAL_GEMM>>>(
        p_cp, p_dWihp, 3648, 0, 0,
        p_gid, 6144, 0, dgru_bih, 0, nullptr, 0, 0, 0, 0);
    k_decgru<<<BN_ * 2 * E_ / 1024, 256>>>(dgru_bhh, hidden);
    // mid = relu(hidden' @ W1'^T + b1)   [8192,1024] K'=6144
    gemm_mma<<<dim3(8, 64, 1), 256, SMEM_TOTAL_GEMM>>>(
        p_hidp, p_W1p, 6144, 0, 0,
        p_mid, 1024, 0, out_b1, 1, nullptr, 0, 0, 0, 0);

    // ---- head ----
    k_out2<<<BN_ / 8, 256>>>(out_W2, out_b2);
    k_max<<<B_, 256>>>();
    k_final<<<BN_ / 256, 256>>>(mask, out);
}